// round 8
// baseline (speedup 1.0000x reference)
#include <cuda_runtime.h>
#include <math.h>

#define E 128
#define C 64
#define TILE_N 64
#define THREADS 256
#define STRIDE 68          // k-major smem stride: 16B-aligned rows
#define EPSV 1e-5f
#define MAXB 1024

__device__ float g_part[MAXB][C + 8];   // per-block partials: [0..63] centroid sums, [64] mask sum
__device__ int   g_count = 0;

__global__ __launch_bounds__(THREADS, 2)
void cd_kernel(const float* __restrict__ node_repr,
               const float* __restrict__ maskp,
               const float* __restrict__ cent,
               float* __restrict__ out, int N) {
    extern __shared__ float smem[];
    float* sn     = smem;                  // [E][STRIDE], 64 node cols used
    float* sc     = sn + E * STRIDE;       // [E][STRIDE], 64 centroid cols used
    float* s_su   = sc + E * STRIDE;       // [64]
    float* s_ru   = s_su + TILE_N;         // [64]  1/(1-su)
    float* s_sv   = s_ru + TILE_N;         // [64]
    float* s_rv   = s_sv + C;              // [64]  1/(1-sv)
    float* s_mask = s_rv + C;              // [64]
    float* s_red  = s_mask + TILE_N;       // [64]
    float* s_red4 = s_red + C;             // [4][64] for parallel final reduce
    __shared__ int   s_last;
    __shared__ float s_msum;

    const int tid = threadIdx.x;
    const int n0  = blockIdx.x * TILE_N;
    float* node_out = out + C;

    // ---- load phase: transpose gmem row-major -> smem k-major (coalesced gmem) ----
    for (int idx = tid; idx < C * E; idx += THREADS) {
        int k = idx & (E - 1);
        int c = idx >> 7;
        sc[k * STRIDE + c] = cent[idx];
    }
    for (int idx = tid; idx < TILE_N * E; idx += THREADS) {
        int k = idx & (E - 1);
        int i = idx >> 7;
        int n = n0 + i;
        sn[k * STRIDE + i] = (n < N) ? node_repr[(size_t)n * E + k] : 0.0f;
    }
    if (tid < TILE_N) {
        int n = n0 + tid;
        s_mask[tid] = (n < N) ? maskp[n] : 0.0f;
        s_red[tid] = 0.0f;
    }
    __syncthreads();

    // ---- norms + reciprocals ----
    if (tid < TILE_N) {
        float s = 0.f;
        #pragma unroll 8
        for (int k = 0; k < E; k++) { float v = sn[k * STRIDE + tid]; s = fmaf(v, v, s); }
        s_su[tid] = s;
        s_ru[tid] = __fdividef(1.0f, 1.0f - s);
    } else if (tid < TILE_N + C) {
        int c = tid - TILE_N;
        float s = 0.f;
        #pragma unroll 8
        for (int k = 0; k < E; k++) { float v = sc[k * STRIDE + c]; s = fmaf(v, v, s); }
        s_sv[c] = s;
        s_rv[c] = __fdividef(1.0f, 1.0f - s);
    }
    __syncthreads();

    // ---- mainloop: 4 nodes x 4 centroids per thread (256 thr = 16x16 tile grid) ----
    const int tx = tid & 15;   // centroid group: 4*tx
    const int ty = tid >> 4;   // node group: 4*ty

    float acc[4][4];
    #pragma unroll
    for (int i = 0; i < 4; i++)
        #pragma unroll
        for (int j = 0; j < 4; j++) acc[i][j] = 0.f;

    const float* snp = sn + 4 * ty;
    const float* scp = sc + 4 * tx;

    #pragma unroll 4
    for (int k = 0; k < E; k++) {
        float4 cv = *(const float4*)(scp + k * STRIDE);
        float4 nv = *(const float4*)(snp + k * STRIDE);
        float nvv[4] = {nv.x, nv.y, nv.z, nv.w};
        #pragma unroll
        for (int i = 0; i < 4; i++) {
            acc[i][0] = fmaf(nvv[i], cv.x, acc[i][0]);
            acc[i][1] = fmaf(nvv[i], cv.y, acc[i][1]);
            acc[i][2] = fmaf(nvv[i], cv.z, acc[i][2]);
            acc[i][3] = fmaf(nvv[i], cv.w, acc[i][3]);
        }
    }

    // ---- epilogue: series acosh (y small since norms << 1), 1 MUFU.RSQ per element ----
    float sv_r[4], rv_r[4];
    #pragma unroll
    for (int j = 0; j < 4; j++) { sv_r[j] = s_sv[4 * tx + j]; rv_r[j] = s_rv[4 * tx + j]; }

    float psum[4] = {0.f, 0.f, 0.f, 0.f};

    #pragma unroll
    for (int i = 0; i < 4; i++) {
        int ln = 4 * ty + i;
        int n  = n0 + ln;
        if (n < N) {
            float su = s_su[ln];
            float ru = s_ru[ln];
            float m  = s_mask[ln];
            float4 o;
            float* op = &o.x;
            #pragma unroll
            for (int j = 0; j < 4; j++) {
                float sq = fmaxf(fmaf(-2.f, acc[i][j], su + sv_r[j]), 0.f);
                float z  = fmaxf(sq * ru * rv_r[j], 0.5f * EPSV);   // z = sq/denom
                float r  = rsqrtf(z);
                float sz = z * r;                                    // sqrt(z)
                float y  = 2.f * z;
                float poly = fmaf(y, fmaf(y, fmaf(y, -0.0055803572f, 0.01875f), -0.083333336f), 1.0f);
                float d  = 2.f * sz * poly * m;                      // acosh(1+y) = sqrt(2y)*poly
                op[j] = d;
                psum[j] += d;
            }
            *(float4*)(node_out + (size_t)n * C + 4 * tx) = o;
        }
    }

    #pragma unroll
    for (int j = 0; j < 4; j++) atomicAdd(&s_red[4 * tx + j], psum[j]);
    __syncthreads();

    // ---- per-block partials ----
    if (tid < C) g_part[blockIdx.x][tid] = s_red[tid];
    if (tid == C) {
        float ms = 0.f;
        #pragma unroll 8
        for (int i = 0; i < TILE_N; i++) ms += s_mask[i];
        g_part[blockIdx.x][C] = ms;
    }
    __threadfence();
    __syncthreads();

    if (tid == 0) s_last = (atomicAdd(&g_count, 1) == (int)gridDim.x - 1);
    __syncthreads();

    // ---- last block reduces all partials (4-way parallel over b) ----
    if (s_last) {
        int nb = gridDim.x;
        int c    = tid & 63;
        int part = tid >> 6;   // 0..3
        float s = 0.f;
        for (int b = part; b < nb; b += 4) s += g_part[b][c];
        s_red4[part * C + c] = s;
        if (tid == 0) {
            float ms = 0.f;
            for (int b = 0; b < nb; b++) ms += g_part[b][C];
            s_msum = ms;
        }
        __syncthreads();
        if (tid < C) {
            float tot = s_red4[tid] + s_red4[C + tid] + s_red4[2 * C + tid] + s_red4[3 * C + tid];
            out[tid] = tot / s_msum;
        }
        if (tid == 0) g_count = 0;   // reset for next graph replay
    }
}

extern "C" void kernel_launch(void* const* d_in, const int* in_sizes, int n_in,
                              void* d_out, int out_size) {
    const float* node_repr = (const float*)d_in[0];
    const float* maskp     = (const float*)d_in[1];
    const float* cent      = (const float*)d_in[2];
    float* out = (float*)d_out;

    int N = in_sizes[1];   // mask element count == node count
    int blocks = (N + TILE_N - 1) / TILE_N;
    if (blocks > MAXB) blocks = MAXB;

    int smem_bytes = (2 * E * STRIDE + 6 * 64 + 4 * C) * (int)sizeof(float);
    cudaFuncSetAttribute(cd_kernel, cudaFuncAttributeMaxDynamicSharedMemorySize, smem_bytes);

    cd_kernel<<<blocks, THREADS, smem_bytes>>>(node_repr, maskp, cent, out, N);
}

// round 9
// speedup vs baseline: 1.0095x; 1.0095x over previous
#include <cuda_runtime.h>
#include <math.h>

#define E 128
#define C 64
#define TILE_N 64
#define THREADS 256
#define EPSV 1e-5f
#define MAXB 1024

typedef unsigned long long u64t;

__device__ float g_part[MAXB][C + 8];   // per-block partials: [0..63] centroid sums, [64] mask sum
__device__ int   g_count = 0;

__device__ __forceinline__ u64t ffma2(u64t a, u64t b, u64t c) {
    u64t d;
    asm("fma.rn.f32x2 %0, %1, %2, %3;" : "=l"(d) : "l"(a), "l"(b), "l"(c));
    return d;
}
__device__ __forceinline__ float f2_sum(u64t a) {
    unsigned int lo, hi;
    asm("mov.b64 {%0, %1}, %2;" : "=r"(lo), "=r"(hi) : "l"(a));
    return __uint_as_float(lo) + __uint_as_float(hi);
}

// Row-major tiles with per-row 16B-chunk XOR swizzle: chunk(row, ci) = row*32 + (ci ^ ((row>>2)&7))
__global__ __launch_bounds__(THREADS, 2)
void cd_kernel(const float* __restrict__ node_repr,
               const float* __restrict__ maskp,
               const float* __restrict__ cent,
               float* __restrict__ out, int N) {
    extern __shared__ float smem[];
    float* sn     = smem;                  // [64][128] node tile (swizzled chunks)
    float* sc     = sn + TILE_N * E;       // [64][128] centroid tile (swizzled chunks)
    float* s_su   = sc + C * E;            // [64]
    float* s_ru   = s_su + TILE_N;         // [64]  1/(1-su)
    float* s_sv   = s_ru + TILE_N;         // [64]
    float* s_rv   = s_sv + C;              // [64]  1/(1-sv)
    float* s_mask = s_rv + C;              // [64]
    float* s_red  = s_mask + TILE_N;       // [64]
    float* s_red4 = s_red + C;             // [4][64]
    __shared__ int   s_last;
    __shared__ float s_msum;

    const int tid = threadIdx.x;
    const int n0  = blockIdx.x * TILE_N;
    float* node_out = out + C;

    // ---- load phase: row-major direct copy, float4 gmem reads, swizzled smem stores ----
    {
        const float4* cent4 = (const float4*)cent;
        const float4* node4 = (const float4*)node_repr;
        float4* sc4 = (float4*)sc;
        float4* sn4 = (float4*)sn;
        #pragma unroll
        for (int it = 0; it < 8; it++) {                 // 64 rows x 32 chunks / 256 thr
            int idx = it * THREADS + tid;
            int row = idx >> 5;
            int ci  = idx & 31;
            int dst = row * 32 + (ci ^ ((row >> 2) & 7));
            sc4[dst] = cent4[idx];
            int n = n0 + row;
            float4 v = make_float4(0.f, 0.f, 0.f, 0.f);
            if (n < N) v = node4[(size_t)n * 32 + ci];
            sn4[dst] = v;
        }
    }
    if (tid < TILE_N) {
        int n = n0 + tid;
        s_mask[tid] = (n < N) ? maskp[n] : 0.0f;
        s_red[tid] = 0.0f;
    }
    __syncthreads();

    // ---- norms + reciprocals ----
    if (tid < TILE_N) {
        int sw = (tid >> 2) & 7;
        const float4* r = (const float4*)(sn + tid * E);
        float s = 0.f;
        #pragma unroll 8
        for (int ci = 0; ci < 32; ci++) {
            float4 v = r[ci ^ sw];
            s = fmaf(v.x, v.x, fmaf(v.y, v.y, fmaf(v.z, v.z, fmaf(v.w, v.w, s))));
        }
        s_su[tid] = s;
        s_ru[tid] = __fdividef(1.0f, 1.0f - s);
    } else if (tid < TILE_N + C) {
        int c = tid - TILE_N;
        int sw = (c >> 2) & 7;
        const float4* r = (const float4*)(sc + c * E);
        float s = 0.f;
        #pragma unroll 8
        for (int ci = 0; ci < 32; ci++) {
            float4 v = r[ci ^ sw];
            s = fmaf(v.x, v.x, fmaf(v.y, v.y, fmaf(v.z, v.z, fmaf(v.w, v.w, s))));
        }
        s_sv[c] = s;
        s_rv[c] = __fdividef(1.0f, 1.0f - s);
    }
    __syncthreads();

    // ---- mainloop: 4 nodes x 4 centroids, FFMA2 packed along K ----
    const int tx = tid & 15;   // centroids 4*tx..4*tx+3   (row>>2 == tx)
    const int ty = tid >> 4;   // nodes     4*ty..4*ty+3   (row>>2 == ty)

    u64t acc[4][4];
    #pragma unroll
    for (int i = 0; i < 4; i++)
        #pragma unroll
        for (int j = 0; j < 4; j++) acc[i][j] = 0ull;

    const ulonglong2* snq = (const ulonglong2*)sn;
    const ulonglong2* scq = (const ulonglong2*)sc;
    const int swc = tx & 7;
    const int swn = ty & 7;

    #pragma unroll 2
    for (int q = 0; q < 32; q++) {       // 32 chunks of 4 k's
        ulonglong2 nv[4], cv[4];
        #pragma unroll
        for (int i = 0; i < 4; i++) nv[i] = snq[(4 * ty + i) * 32 + (q ^ swn)];
        #pragma unroll
        for (int j = 0; j < 4; j++) cv[j] = scq[(4 * tx + j) * 32 + (q ^ swc)];
        #pragma unroll
        for (int i = 0; i < 4; i++)
            #pragma unroll
            for (int j = 0; j < 4; j++) {
                acc[i][j] = ffma2(nv[i].x, cv[j].x, acc[i][j]);
                acc[i][j] = ffma2(nv[i].y, cv[j].y, acc[i][j]);
            }
    }

    // ---- epilogue: series acosh (norms << 1), 1 MUFU.RSQ per element ----
    float sv_r[4], rv_r[4];
    #pragma unroll
    for (int j = 0; j < 4; j++) { sv_r[j] = s_sv[4 * tx + j]; rv_r[j] = s_rv[4 * tx + j]; }

    float psum[4] = {0.f, 0.f, 0.f, 0.f};

    #pragma unroll
    for (int i = 0; i < 4; i++) {
        int ln = 4 * ty + i;
        int n  = n0 + ln;
        if (n < N) {
            float su = s_su[ln];
            float ru = s_ru[ln];
            float m  = s_mask[ln];
            float4 o;
            float* op = &o.x;
            #pragma unroll
            for (int j = 0; j < 4; j++) {
                float dot = f2_sum(acc[i][j]);
                float sq = fmaxf(fmaf(-2.f, dot, su + sv_r[j]), 0.f);
                float z  = fmaxf(sq * ru * rv_r[j], 0.5f * EPSV);   // z = sq/denom
                float r  = rsqrtf(z);
                float sz = z * r;                                    // sqrt(z)
                float y  = 2.f * z;
                float poly = fmaf(y, fmaf(y, fmaf(y, -0.0055803572f, 0.01875f), -0.083333336f), 1.0f);
                float d  = 2.f * sz * poly * m;                      // acosh(1+y) = sqrt(2y)*poly
                op[j] = d;
                psum[j] += d;
            }
            *(float4*)(node_out + (size_t)n * C + 4 * tx) = o;
        }
    }

    #pragma unroll
    for (int j = 0; j < 4; j++) atomicAdd(&s_red[4 * tx + j], psum[j]);
    __syncthreads();

    // ---- per-block partials ----
    if (tid < C) g_part[blockIdx.x][tid] = s_red[tid];
    if (tid == C) {
        float ms = 0.f;
        #pragma unroll 8
        for (int i = 0; i < TILE_N; i++) ms += s_mask[i];
        g_part[blockIdx.x][C] = ms;
    }
    __threadfence();
    __syncthreads();

    if (tid == 0) s_last = (atomicAdd(&g_count, 1) == (int)gridDim.x - 1);
    __syncthreads();

    // ---- last block reduces all partials (4-way parallel over blocks) ----
    if (s_last) {
        int nb = gridDim.x;
        int c    = tid & 63;
        int part = tid >> 6;   // 0..3
        float s = 0.f;
        for (int b = part; b < nb; b += 4) s += g_part[b][c];
        s_red4[part * C + c] = s;
        if (tid == 0) {
            float ms = 0.f;
            for (int b = 0; b < nb; b++) ms += g_part[b][C];
            s_msum = ms;
        }
        __syncthreads();
        if (tid < C) {
            float tot = s_red4[tid] + s_red4[C + tid] + s_red4[2 * C + tid] + s_red4[3 * C + tid];
            out[tid] = tot / s_msum;
        }
        if (tid == 0) g_count = 0;   // reset for next graph replay
    }
}

extern "C" void kernel_launch(void* const* d_in, const int* in_sizes, int n_in,
                              void* d_out, int out_size) {
    const float* node_repr = (const float*)d_in[0];
    const float* maskp     = (const float*)d_in[1];
    const float* cent      = (const float*)d_in[2];
    float* out = (float*)d_out;

    int N = in_sizes[1];   // mask element count == node count
    int blocks = (N + TILE_N - 1) / TILE_N;
    if (blocks > MAXB) blocks = MAXB;

    int smem_bytes = (TILE_N * E + C * E + 6 * 64 + 4 * C) * (int)sizeof(float);
    cudaFuncSetAttribute(cd_kernel, cudaFuncAttributeMaxDynamicSharedMemorySize, smem_bytes);

    cd_kernel<<<blocks, THREADS, smem_bytes>>>(node_repr, maskp, cent, out, N);
}

// round 12
// speedup vs baseline: 1.7663x; 1.7496x over previous
#include <cuda_runtime.h>
#include <cstdint>
#include <math.h>

#define E 128
#define C 64
#define TILE_M 128
#define THREADS 256
#define EPSV 1e-5f
#define MAXB 512
#define SA_STRIDE 132   // floats; bank = (4*row_in_8 + tg) -> conflict-free fragments
#define SB_STRIDE 132   // floats; same map (K=128 per row + 4 pad)

__device__ float g_part[MAXB][C + 8];
__device__ int   g_count = 0;

__device__ __forceinline__ uint32_t cvt_tf32(float f) {
    uint32_t r;
    asm("cvt.rna.tf32.f32 %0, %1;" : "=r"(r) : "f"(f));
    return r;
}

__device__ __forceinline__ void mma_tf32(float c[4], const uint32_t a[4], const uint32_t b[2]) {
    asm volatile(
        "mma.sync.aligned.m16n8k8.row.col.f32.tf32.tf32.f32 "
        "{%0,%1,%2,%3}, {%4,%5,%6,%7}, {%8,%9}, {%0,%1,%2,%3};"
        : "+f"(c[0]), "+f"(c[1]), "+f"(c[2]), "+f"(c[3])
        : "r"(a[0]), "r"(a[1]), "r"(a[2]), "r"(a[3]), "r"(b[0]), "r"(b[1]));
}

__global__ __launch_bounds__(THREADS, 2)
void cd_kernel(const float* __restrict__ node_repr,
               const float* __restrict__ maskp,
               const float* __restrict__ cent,
               float* __restrict__ out, int N) {
    extern __shared__ float smem[];
    float* sA = smem;                        // [128][SA_STRIDE], tf32-rounded
    float* sB = sA + TILE_M * SA_STRIDE;     // [64][SB_STRIDE],  tf32-rounded
    __shared__ float s_su[TILE_M], s_ru[TILE_M], s_sv[C], s_rv[C], s_mask[TILE_M];
    __shared__ float s_red[C];
    __shared__ float s_red4[4][C];
    __shared__ int s_last;
    __shared__ float s_msum;

    const int tid  = threadIdx.x;
    const int wid  = tid >> 5;
    const int lane = tid & 31;
    const int g    = lane >> 2;   // groupID
    const int tg   = lane & 3;    // thread-in-group
    const int n0   = blockIdx.x * TILE_M;
    float* node_out = out + C;

    if (tid < C) s_red[tid] = 0.0f;
    if (tid < TILE_M) {
        int n = n0 + tid;
        s_mask[tid] = (n < N) ? maskp[n] : 0.0f;
    }

    // ---- load tiles (row-major), tf32-round, norms via warp shuffle ----
    {
        const float4* node4 = (const float4*)node_repr;
        #pragma unroll
        for (int it = 0; it < 16; it++) {     // A: 128 rows x 32 float4
            int idx = it * THREADS + tid;
            int row = idx >> 5;               // warp-uniform
            int ci  = idx & 31;
            int n = n0 + row;
            float4 v = make_float4(0.f, 0.f, 0.f, 0.f);
            if (n < N) v = node4[(size_t)n * 32 + ci];
            float4 t;
            t.x = __uint_as_float(cvt_tf32(v.x));
            t.y = __uint_as_float(cvt_tf32(v.y));
            t.z = __uint_as_float(cvt_tf32(v.z));
            t.w = __uint_as_float(cvt_tf32(v.w));
            *(float4*)(sA + row * SA_STRIDE + 4 * ci) = t;
            float s = fmaf(t.x, t.x, fmaf(t.y, t.y, fmaf(t.z, t.z, t.w * t.w)));
            #pragma unroll
            for (int off = 16; off > 0; off >>= 1) s += __shfl_xor_sync(0xFFFFFFFFu, s, off);
            if (lane == 0) s_su[row] = s;
        }
        const float4* cent4 = (const float4*)cent;
        #pragma unroll
        for (int it = 0; it < 8; it++) {      // B: 64 rows x 32 float4
            int idx = it * THREADS + tid;
            int row = idx >> 5;
            int ci  = idx & 31;
            float4 v = cent4[idx];
            float4 t;
            t.x = __uint_as_float(cvt_tf32(v.x));
            t.y = __uint_as_float(cvt_tf32(v.y));
            t.z = __uint_as_float(cvt_tf32(v.z));
            t.w = __uint_as_float(cvt_tf32(v.w));
            *(float4*)(sB + row * SB_STRIDE + 4 * ci) = t;
            float s = fmaf(t.x, t.x, fmaf(t.y, t.y, fmaf(t.z, t.z, t.w * t.w)));
            #pragma unroll
            for (int off = 16; off > 0; off >>= 1) s += __shfl_xor_sync(0xFFFFFFFFu, s, off);
            if (lane == 0) s_sv[row] = s;
        }
    }
    __syncthreads();

    if (tid < TILE_M) {
        s_ru[tid] = __fdividef(1.0f, 1.0f - s_su[tid]);
    } else if (tid < TILE_M + C) {
        int c = tid - TILE_M;
        s_rv[c] = __fdividef(1.0f, 1.0f - s_sv[c]);
    }
    __syncthreads();

    // ---- mainloop: each warp -> 32x32 tile via m16n8k8 tf32 mma.sync ----
    const int m0 = (wid & 3) * 32;            // node rows
    const int nq = (wid >> 2) * 32;           // centroid cols

    float cfr[2][4][4];
    #pragma unroll
    for (int mf = 0; mf < 2; mf++)
        #pragma unroll
        for (int nf = 0; nf < 4; nf++)
            #pragma unroll
            for (int r = 0; r < 4; r++) cfr[mf][nf][r] = 0.f;

    #pragma unroll
    for (int ks = 0; ks < 16; ks++) {
        const int k = ks * 8;
        uint32_t a[2][4], b[4][2];
        #pragma unroll
        for (int mf = 0; mf < 2; mf++) {
            const float* ar0 = sA + (m0 + mf * 16 + g) * SA_STRIDE + k + tg;
            a[mf][0] = __float_as_uint(ar0[0]);
            a[mf][2] = __float_as_uint(ar0[4]);
            a[mf][1] = __float_as_uint(ar0[8 * SA_STRIDE]);
            a[mf][3] = __float_as_uint(ar0[8 * SA_STRIDE + 4]);
        }
        #pragma unroll
        for (int nf = 0; nf < 4; nf++) {
            const float* br = sB + (nq + nf * 8 + g) * SB_STRIDE + k + tg;
            b[nf][0] = __float_as_uint(br[0]);
            b[nf][1] = __float_as_uint(br[4]);
        }
        #pragma unroll
        for (int mf = 0; mf < 2; mf++)
            #pragma unroll
            for (int nf = 0; nf < 4; nf++)
                mma_tf32(cfr[mf][nf], a[mf], b[nf]);
    }

    // ---- epilogue: series acosh, stores, graph partial sums ----
    float sv_c[4][2], rv_c[4][2];
    #pragma unroll
    for (int nf = 0; nf < 4; nf++) {
        int cc = nq + nf * 8 + 2 * tg;
        sv_c[nf][0] = s_sv[cc];     rv_c[nf][0] = s_rv[cc];
        sv_c[nf][1] = s_sv[cc + 1]; rv_c[nf][1] = s_rv[cc + 1];
    }

    float psum[4][2];
    #pragma unroll
    for (int nf = 0; nf < 4; nf++) { psum[nf][0] = 0.f; psum[nf][1] = 0.f; }

    #pragma unroll
    for (int mf = 0; mf < 2; mf++) {
        #pragma unroll
        for (int half = 0; half < 2; half++) {
            int row = m0 + mf * 16 + g + half * 8;
            int n   = n0 + row;
            float su = s_su[row];
            float ru = s_ru[row];
            float m  = s_mask[row];
            #pragma unroll
            for (int nf = 0; nf < 4; nf++) {
                float2 o;
                #pragma unroll
                for (int p = 0; p < 2; p++) {
                    float dot = cfr[mf][nf][half * 2 + p];
                    float sq  = fmaxf(fmaf(-2.f, dot, su + sv_c[nf][p]), 0.f);
                    float z   = fmaxf(sq * ru * rv_c[nf][p], 0.5f * EPSV);
                    float r   = rsqrtf(z);
                    float sz  = z * r;                        // sqrt(z)
                    float y   = 2.f * z;
                    float poly = fmaf(y, fmaf(y, fmaf(y, -0.0055803572f, 0.01875f), -0.083333336f), 1.0f);
                    float d   = 2.f * sz * poly * m;          // acosh(1+y) = sqrt(2y)*poly
                    ((float*)&o)[p] = d;
                    psum[nf][p] += d;
                }
                if (n < N)
                    *(float2*)(node_out + (size_t)n * C + nq + nf * 8 + 2 * tg) = o;
            }
        }
    }

    // reduce psum over groupID (8 groups) -> full 32-row column sums
    #pragma unroll
    for (int nf = 0; nf < 4; nf++)
        #pragma unroll
        for (int p = 0; p < 2; p++) {
            float s = psum[nf][p];
            s += __shfl_xor_sync(0xFFFFFFFFu, s, 4);
            s += __shfl_xor_sync(0xFFFFFFFFu, s, 8);
            s += __shfl_xor_sync(0xFFFFFFFFu, s, 16);
            psum[nf][p] = s;
        }
    if (g == 0) {
        #pragma unroll
        for (int nf = 0; nf < 4; nf++) {
            atomicAdd(&s_red[nq + nf * 8 + 2 * tg], psum[nf][0]);
            atomicAdd(&s_red[nq + nf * 8 + 2 * tg + 1], psum[nf][1]);
        }
    }
    __syncthreads();

    // ---- per-block partials ----
    if (tid < C) g_part[blockIdx.x][tid] = s_red[tid];
    if (tid == C) {
        float ms = 0.f;
        #pragma unroll 8
        for (int i = 0; i < TILE_M; i++) ms += s_mask[i];
        g_part[blockIdx.x][C] = ms;
    }
    __threadfence();
    __syncthreads();

    if (tid == 0) s_last = (atomicAdd(&g_count, 1) == (int)gridDim.x - 1);
    __syncthreads();

    // ---- last block reduces all partials ----
    if (s_last) {
        int nb = gridDim.x;
        int c    = tid & 63;
        int part = tid >> 6;
        float s = 0.f;
        for (int b = part; b < nb; b += 4) s += g_part[b][c];
        s_red4[part][c] = s;
        if (tid == 0) {
            float ms = 0.f;
            for (int b = 0; b < nb; b++) ms += g_part[b][C];
            s_msum = ms;
        }
        __syncthreads();
        if (tid < C)
            out[tid] = (s_red4[0][tid] + s_red4[1][tid] + s_red4[2][tid] + s_red4[3][tid]) / s_msum;
        if (tid == 0) g_count = 0;
    }
}

extern "C" void kernel_launch(void* const* d_in, const int* in_sizes, int n_in,
                              void* d_out, int out_size) {
    const float* node_repr = (const float*)d_in[0];
    const float* maskp     = (const float*)d_in[1];
    const float* cent      = (const float*)d_in[2];
    float* out = (float*)d_out;

    int N = in_sizes[1];
    int blocks = (N + TILE_M - 1) / TILE_M;
    if (blocks > MAXB) blocks = MAXB;

    int smem_bytes = (TILE_M * SA_STRIDE + C * SB_STRIDE) * (int)sizeof(float);
    cudaFuncSetAttribute(cd_kernel, cudaFuncAttributeMaxDynamicSharedMemorySize, smem_bytes);

    cd_kernel<<<blocks, THREADS, smem_bytes>>>(node_repr, maskp, cent, out, N);
}